// round 16
// baseline (speedup 1.0000x reference)
#include <cuda_runtime.h>
#include <math.h>

typedef unsigned int u32;
typedef unsigned long long u64;

#define CIN   1024
#define COUT  512
#define NPIX  4096
#define NANCH 36864
#define SORTN 65536
#define NPRE  12000
#define NPOST 2000
#define NWORD 188   /* ceil(12000/64) */

#define OFF_LOC  0
#define OFF_SC   147456
#define OFF_ROIS 221184
#define OFF_ANC  229184

#define XSTR 68
#define XIC  (4 * XSTR)          /* 272 floats per ic */
#define XS_FLOATS (8 * XIC)      /* 2176 */
#define WS_FLOATS (72 * 64)      /* 4608 */
#define CONV_SMEM_FLOATS (2 * XS_FLOATS + 2 * WS_FLOATS)   /* 54272 B */

__device__ __align__(16) float g_h[COUT * NPIX];
__device__ __align__(16) float g_wt[9216 * 512];
__device__ __align__(16) float g_wh[COUT * 56];
__device__ __align__(16) float g_boxes[NANCH * 4];
__device__ u64 g_keys[SORTN];
__device__ __align__(16) float g_sboxes[NPRE * 4];
__device__ int g_valid[NPRE];
__device__ u64 g_mask[(size_t)NPRE * NWORD];
__device__ unsigned g_barcnt = 0;
__device__ unsigned g_bargen = 0;

#define FMA2(d, a, b) asm("fma.rn.f32x2 %0, %1, %2, %0;" : "+l"(d) : "l"(a), "l"(b))
#define ADD2(d, a, b) asm("add.rn.f32x2 %0, %1, %2;" : "=l"(d) : "l"(a), "l"(b))
#define PK2(d, lo, hi) asm("mov.b64 %0, {%1, %2};" : "=l"(d) : "f"(lo), "f"(hi))
#define UPK2(lo, hi, s) asm("mov.b64 {%0, %1}, %2;" : "=f"(lo), "=f"(hi) : "l"(s))
#define NEGMASK2 0x8000000080000000ull

#define CP_ASYNC4(dst_u32, src_ptr, srcsz) \
    asm volatile("cp.async.ca.shared.global [%0], [%1], 4, %2;" \
                 :: "r"(dst_u32), "l"(src_ptr), "r"(srcsz))
#define CP_COMMIT()  asm volatile("cp.async.commit_group;")
#define CP_WAIT0()   asm volatile("cp.async.wait_group 0;" ::: "memory")

// ---------------------------------------------------------------------------
__global__ void zero_rois(float* __restrict__ out) {
    int i = blockIdx.x * 256 + threadIdx.x;
    if (i < NPOST * 4) out[OFF_ROIS + i] = 0.f;
}

// ---------------------------------------------------------------------------
__global__ void __launch_bounds__(256) prep_wt(const float* __restrict__ w) {
    __shared__ float tile[32][33];
    const int j0  = blockIdx.x * 32;
    const int oc0 = blockIdx.y * 32;
    const int tx = threadIdx.x & 31, ty = threadIdx.x >> 5;
#pragma unroll
    for (int r = 0; r < 4; ++r)
        tile[ty + r * 8][tx] = w[(size_t)(oc0 + ty + r * 8) * 9216 + j0 + tx];
    __syncthreads();
#pragma unroll
    for (int r = 0; r < 4; ++r)
        g_wt[(size_t)(j0 + ty + r * 8) * 512 + oc0 + tx] = tile[tx][ty + r * 8];
}

// ---------------------------------------------------------------------------
__global__ void prep_w(const float* __restrict__ score_w, const float* __restrict__ loc_w) {
    int idx = blockIdx.x * 256 + threadIdx.x;
    if (idx >= 512 * 56) return;
    int c = idx / 56, o = idx - c * 56;
    float v = 0.f;
    if (o < 36) v = loc_w[o * 512 + c];
    else if (o < 54) v = score_w[(o - 36) * 512 + c];
    g_wh[idx] = v;
}

// ---------------------------------------------------------------------------
__device__ __forceinline__ void conv_stage(const float* __restrict__ x,
                                           int y0, int chunk, int oc0,
                                           u32 xs_u, u32 ws_u,
                                           int x_ic0, int x_r0, int x_c0, int tid) {
    const int ic0 = chunk << 3;
    {
        int ic = x_ic0, r = x_r0, cc = x_c0;
        int sidx = tid;
#pragma unroll
        for (int l = 0; l < 9; ++l) {
            if (ic < 8) {
                int iy  = y0 - 1 + r;
                int ixc = cc - 1;
                bool ok = (cc < 66) && ((unsigned)iy < 64u) && ((unsigned)ixc < 64u);
                const float* src = ok ? (x + (ic0 + ic) * 4096 + iy * 64 + ixc) : x;
                unsigned ss = ok ? 4u : 0u;
                CP_ASYNC4(xs_u + sidx * 4, src, ss);
            }
            sidx += 256;
            cc += 52; r += 3;
            if (cc >= XSTR) { cc -= XSTR; r += 1; }
            if (r >= 4) { r -= 4; ic += 1; }
        }
    }
    {
        const size_t base = (size_t)(ic0 * 9) * 512 + oc0;
#pragma unroll
        for (int l = 0; l < 18; ++l) {
            int idx = tid + l * 256;
            int k = idx >> 6, oc = idx & 63;
            CP_ASYNC4(ws_u + idx * 4, &g_wt[base + (size_t)k * 512 + oc], 4u);
        }
    }
    CP_COMMIT();
}

// ---------------------------------------------------------------------------
__global__ void __launch_bounds__(256, 2) conv3_lrelu(const float* __restrict__ x,
                                                      const float* __restrict__ bias) {
    extern __shared__ float dsm[];
    float* xsb[2] = { dsm, dsm + XS_FLOATS };
    float* wsb[2] = { dsm + 2 * XS_FLOATS, dsm + 2 * XS_FLOATS + WS_FLOATS };
    const u32 dsm_u = (u32)__cvta_generic_to_shared(dsm);
    const u32 xs_u[2] = { dsm_u, dsm_u + XS_FLOATS * 4 };
    const u32 ws_u[2] = { dsm_u + 2 * XS_FLOATS * 4, dsm_u + (2 * XS_FLOATS + WS_FLOATS) * 4 };

    const int oc0 = blockIdx.x * 64;
    const int y0  = blockIdx.y * 2;
    const int tid = threadIdx.x;
    const int tx = tid & 15, ty = tid >> 4;
    const int ry  = tx >> 3;
    const int cx0 = (tx & 7) << 3;
    const int ocl = ty << 2;

    u64 part2[2][8], acc2[2][8], ncmp2[2][8];
#pragma unroll
    for (int o = 0; o < 2; ++o)
#pragma unroll
        for (int p = 0; p < 8; ++p) { part2[o][p] = 0ull; acc2[o][p] = 0ull; ncmp2[o][p] = 0ull; }

    const int x_ic0 = tid / XIC;
    const int x_rem0 = tid - x_ic0 * XIC;
    const int x_r0 = x_rem0 / XSTR;
    const int x_c0 = x_rem0 - x_r0 * XSTR;

    conv_stage(x, y0, 0, oc0, xs_u[0], ws_u[0], x_ic0, x_r0, x_c0, tid);
    CP_WAIT0();
    __syncthreads();

#pragma unroll 1
    for (int chunk = 0; chunk < CIN / 8; ++chunk) {
        const int cur = chunk & 1;
        if (chunk + 1 < CIN / 8)
            conv_stage(x, y0, chunk + 1, oc0, xs_u[1 - cur], ws_u[1 - cur],
                       x_ic0, x_r0, x_c0, tid);
        const float* xs = xsb[cur];
        const float* ws = wsb[cur];
#pragma unroll 1
        for (int ic = 0; ic < 8; ++ic) {
#pragma unroll
            for (int ky = 0; ky < 3; ++ky) {
                const float4* xr = (const float4*)&xs[ic * XIC + (ry + ky) * XSTR + cx0];
                float xv[12];
                *(float4*)(xv)     = xr[0];
                *(float4*)(xv + 4) = xr[1];
                *(float4*)(xv + 8) = xr[2];
                u64 xb[10];
#pragma unroll
                for (int i = 0; i < 10; ++i) PK2(xb[i], xv[i], xv[i]);
#pragma unroll
                for (int kx = 0; kx < 3; ++kx) {
                    const float4 wq = *(const float4*)&ws[(ic * 9 + ky * 3 + kx) * 64 + ocl];
                    u64 wp0, wp1;
                    PK2(wp0, wq.x, wq.y);
                    PK2(wp1, wq.z, wq.w);
#pragma unroll
                    for (int p = 0; p < 8; ++p) {
                        FMA2(part2[0][p], wp0, xb[p + kx]);
                        FMA2(part2[1][p], wp1, xb[p + kx]);
                    }
                }
            }
        }
        if (chunk & 1) {
#pragma unroll
            for (int o = 0; o < 2; ++o)
#pragma unroll
                for (int p = 0; p < 8; ++p) {
                    u64 y, t, s;
                    ADD2(y, part2[o][p], ncmp2[o][p]);
                    ADD2(t, acc2[o][p], y);
                    u64 tn = t ^ NEGMASK2;
                    ADD2(s, acc2[o][p], tn);
                    ADD2(ncmp2[o][p], s, y);
                    acc2[o][p] = t;
                    part2[o][p] = 0ull;
                }
        }
        if (chunk + 1 < CIN / 8) CP_WAIT0();
        __syncthreads();
    }
    const int row = y0 + ry;
#pragma unroll
    for (int o = 0; o < 2; ++o)
#pragma unroll
        for (int p = 0; p < 8; ++p) {
            float a0, a1;
            UPK2(a0, a1, acc2[o][p]);
            int oc = oc0 + ocl + 2 * o;
            float v0 = a0 + bias[oc];
            float v1 = a1 + bias[oc + 1];
            v0 = v0 > 0.f ? v0 : 0.01f * v0;
            v1 = v1 > 0.f ? v1 : 0.01f * v1;
            g_h[oc * 4096 + row * 64 + cx0 + p] = v0;
            g_h[(oc + 1) * 4096 + row * 64 + cx0 + p] = v1;
        }
}

// ---------------------------------------------------------------------------
__global__ void __launch_bounds__(256) heads_kernel(float* __restrict__ out,
                                                    const float* __restrict__ loc_b,
                                                    const float* __restrict__ score_b) {
    __shared__ float hs[64 * 32];
    __shared__ float wsm[64 * 56];
    const int px0 = blockIdx.x * 32;
    const int tid = threadIdx.x;
    const int px = tid & 31, lane = tid >> 5;
    float acc[7], comp[7];
#pragma unroll
    for (int j = 0; j < 7; ++j) { acc[j] = 0.f; comp[j] = 0.f; }

    for (int ch = 0; ch < 8; ++ch) {
        const int c0 = ch * 64;
#pragma unroll
        for (int l = 0; l < 8; ++l) {
            int idx = tid + l * 256;
            int c = idx >> 5, pp = idx & 31;
            hs[idx] = g_h[(c0 + c) * 4096 + px0 + pp];
        }
#pragma unroll
        for (int l = 0; l < 14; ++l) {
            int idx = tid + l * 256;
            wsm[idx] = g_wh[c0 * 56 + idx];
        }
        __syncthreads();
        float part[7];
#pragma unroll
        for (int j = 0; j < 7; ++j) part[j] = 0.f;
#pragma unroll 4
        for (int c = 0; c < 64; ++c) {
            float hv = hs[c * 32 + px];
#pragma unroll
            for (int j = 0; j < 7; ++j)
                part[j] = __fmaf_rn(hv, wsm[c * 56 + lane * 7 + j], part[j]);
        }
#pragma unroll
        for (int j = 0; j < 7; ++j) {
            float y = __fsub_rn(part[j], comp[j]);
            float t = __fadd_rn(acc[j], y);
            comp[j] = __fsub_rn(__fsub_rn(t, acc[j]), y);
            acc[j] = t;
        }
        __syncthreads();
    }
    const int p = px0 + px;
#pragma unroll
    for (int j = 0; j < 7; ++j) {
        int o = lane * 7 + j;
        if (o < 36) {
            int a = o >> 2, cc = o & 3;
            out[OFF_LOC + (p * 9 + a) * 4 + cc] = acc[j] + loc_b[o];
        } else if (o < 54) {
            int s = o - 36;
            int a = s >> 1, cc = s & 1;
            out[OFF_SC + (p * 9 + a) * 2 + cc] = acc[j] + score_b[s];
        }
    }
}

// ---------------------------------------------------------------------------
__global__ void decode_kernel(float* __restrict__ out) {
    int idx = blockIdx.x * 256 + threadIdx.x;
    if (idx >= SORTN) return;
    if (idx >= NANCH) { g_keys[idx] = ~0ull; return; }

    int a = idx % 9;
    int p = idx / 9;
    int yy = p >> 6, xx = p & 63;

    const double ratios[3] = {0.5, 1.0, 2.0};
    const double scales[3] = {8.0, 16.0, 32.0};
    double r = ratios[a / 3], s = scales[a % 3];
    double hh = 16.0 * s * sqrt(r);
    double ww = 16.0 * s * sqrt(1.0 / r);
    float by1 = (float)(8.0 - hh / 2.0);
    float bx1 = (float)(8.0 - ww / 2.0);
    float by2 = (float)(8.0 + hh / 2.0);
    float bx2 = (float)(8.0 + ww / 2.0);
    float sy = (float)yy * 16.0f, sx = (float)xx * 16.0f;
    float a0 = sy + by1, a1 = sx + bx1, a2 = sy + by2, a3 = sx + bx2;

    out[OFF_ANC + idx * 4 + 0] = a0;
    out[OFF_ANC + idx * 4 + 1] = a1;
    out[OFF_ANC + idx * 4 + 2] = a2;
    out[OFF_ANC + idx * 4 + 3] = a3;

    float l0 = out[OFF_LOC + idx * 4 + 0];
    float l1 = out[OFF_LOC + idx * 4 + 1];
    float l2 = out[OFF_LOC + idx * 4 + 2];
    float l3 = out[OFF_LOC + idx * 4 + 3];
    float s0 = out[OFF_SC + idx * 2 + 0];
    float s1 = out[OFF_SC + idx * 2 + 1];

    double d0 = (double)s0, d1 = (double)s1;
    double m  = fmax(d0, d1);
    double e0 = exp(d0 - m), e1 = exp(d1 - m);
    float fg = (float)(e1 / (e0 + e1));

    float ha = a2 - a0, wa = a3 - a1;
    float cya = a0 + 0.5f * ha, cxa = a1 + 0.5f * wa;
    float cy = l0 * ha + cya;
    float cx = l1 * wa + cxa;
    float bh = ha * expf(l2);
    float bw = wa * expf(l3);
    g_boxes[idx * 4 + 0] = cy - 0.5f * bh;
    g_boxes[idx * 4 + 1] = cx - 0.5f * bw;
    g_boxes[idx * 4 + 2] = cy + 0.5f * bh;
    g_boxes[idx * 4 + 3] = cx + 0.5f * bw;

    unsigned ub = __float_as_uint(fg);
    g_keys[idx] = ((u64)(ub ^ 0xFFFFFFFFu) << 32) | (unsigned)idx;
}

// ---------------------------------------------------------------------------
__device__ __forceinline__ void cmpswap(u64& a, u64& b, bool up) {
    if ((a > b) == up) { u64 t = a; a = b; b = t; }
}

__device__ __forceinline__ void gridbar() {
    __syncthreads();
    if (threadIdx.x == 0) {
        __threadfence();
        unsigned gen = atomicAdd(&g_bargen, 0u);
        if (atomicAdd(&g_barcnt, 1u) == gridDim.x - 1) {
            g_barcnt = 0;
            __threadfence();
            atomicAdd(&g_bargen, 1u);
        } else {
            while (atomicAdd(&g_bargen, 0u) == gen) {}
        }
        __threadfence();
    }
    __syncthreads();
}

__device__ __forceinline__ void local_step(u64* s, int base, int j, int k, int t) {
#pragma unroll
    for (int m = 0; m < 2; ++m) {
        int pr = t + m * 1024;
        int i = ((pr & ~(j - 1)) << 1) | (pr & (j - 1));
        int p = i | j;
        bool up = (((base + i) & k) == 0);
        u64 a = s[i], b = s[p];
        if ((a > b) == up) { s[i] = b; s[p] = a; }
    }
}

__global__ void __launch_bounds__(1024) megasort(const int* __restrict__ imh,
                                                 const int* __restrict__ imw) {
    __shared__ u64 s[4096];
    const int b = blockIdx.x;
    const int base = b * 4096;
    const int t = threadIdx.x;
    const int gq = b * 1024 + t;

#pragma unroll
    for (int m = 0; m < 4; ++m) s[t + m * 1024] = g_keys[base + t + m * 1024];
    __syncthreads();

    for (int k = 2; k <= 4096; k <<= 1)
        for (int j = k >> 1; j > 0; j >>= 1) { local_step(s, base, j, k, t); __syncthreads(); }

    for (int k = 8192; k <= 65536; k <<= 1) {
#pragma unroll
        for (int m = 0; m < 4; ++m) g_keys[base + t + m * 1024] = s[t + m * 1024];
        gridbar();
        int j = k >> 1;
        while (j >= 4096) {
            if (j >= 8192) {
                int a = j >> 1;
                int low = gq & (a - 1);
                int i = ((gq & ~(a - 1)) << 2) | low;
                u64 v0 = g_keys[i];
                u64 v1 = g_keys[i + a];
                u64 v2 = g_keys[i + 2 * a];
                u64 v3 = g_keys[i + 3 * a];
                bool up = ((i & k) == 0);
                cmpswap(v0, v2, up); cmpswap(v1, v3, up);
                cmpswap(v0, v1, up); cmpswap(v2, v3, up);
                g_keys[i] = v0;
                g_keys[i + a] = v1;
                g_keys[i + 2 * a] = v2;
                g_keys[i + 3 * a] = v3;
                j >>= 2;
            } else {
#pragma unroll
                for (int m = 0; m < 2; ++m) {
                    int p = gq + m * 16384;
                    int i = ((p & ~(j - 1)) << 1) | (p & (j - 1));
                    int q = i | j;
                    bool up = ((i & k) == 0);
                    u64 a = g_keys[i], bb = g_keys[q];
                    if ((a > bb) == up) { g_keys[i] = bb; g_keys[q] = a; }
                }
                j >>= 1;
            }
            gridbar();
        }
#pragma unroll
        for (int m = 0; m < 4; ++m) s[t + m * 1024] = g_keys[base + t + m * 1024];
        __syncthreads();
        for (int j2 = 2048; j2 > 0; j2 >>= 1) { local_step(s, base, j2, k, t); __syncthreads(); }
    }

    if (base < NPRE) {
        float H = (float)(*imh), W = (float)(*imw);
#pragma unroll
        for (int m = 0; m < 4; ++m) {
            int gi = base + t + m * 1024;
            if (gi < NPRE) {
                unsigned idx = (unsigned)s[t + m * 1024];
                float b0 = g_boxes[idx * 4 + 0];
                float b1 = g_boxes[idx * 4 + 1];
                float b2 = g_boxes[idx * 4 + 2];
                float b3 = g_boxes[idx * 4 + 3];
                b0 = fminf(fmaxf(b0, 0.f), H);
                b1 = fminf(fmaxf(b1, 0.f), W);
                b2 = fminf(fmaxf(b2, 0.f), H);
                b3 = fminf(fmaxf(b3, 0.f), W);
                g_sboxes[gi * 4 + 0] = b0;
                g_sboxes[gi * 4 + 1] = b1;
                g_sboxes[gi * 4 + 2] = b2;
                g_sboxes[gi * 4 + 3] = b3;
                g_valid[gi] = ((b2 - b0) >= 16.f) && ((b3 - b1) >= 16.f);
            }
        }
    }
}

// ---------------------------------------------------------------------------
__global__ void __launch_bounds__(256) nms_mask() {
    const int colb = blockIdx.x;
    const int rowb4 = blockIdx.y;
    if (colb < rowb4 * 4) return;
    __shared__ __align__(16) float cb[64 * 4];
    const int cbase = colb * 64;
    const int cs = min(64, NPRE - cbase);
    const int t = threadIdx.x;
    if (t < cs) ((float4*)cb)[t] = ((const float4*)g_sboxes)[cbase + t];
    __syncthreads();
    const int rowb = rowb4 * 4 + (t >> 6);
    const int tr = t & 63;
    if (colb < rowb) return;
    const int i = rowb * 64 + tr;
    if (i >= NPRE) return;
    float y1 = g_sboxes[i * 4 + 0], x1 = g_sboxes[i * 4 + 1];
    float y2 = g_sboxes[i * 4 + 2], x2 = g_sboxes[i * 4 + 3];
    float ai = (y2 - y1) * (x2 - x1);
    u64 bits = 0;
    int j0 = (rowb == colb) ? (tr + 1) : 0;
    for (int j = j0; j < cs; ++j) {
        float cy1 = cb[j * 4 + 0], cx1 = cb[j * 4 + 1];
        float cy2 = cb[j * 4 + 2], cx2 = cb[j * 4 + 3];
        float yy1 = fmaxf(y1, cy1), xx1 = fmaxf(x1, cx1);
        float yy2 = fminf(y2, cy2), xx2 = fminf(x2, cx2);
        float inter = fmaxf(yy2 - yy1, 0.f) * fmaxf(xx2 - xx1, 0.f);
        float aj = (cy2 - cy1) * (cx2 - cx1);
        float iou = inter / (ai + aj - inter + 1e-10f);
        if (iou > 0.7f) bits |= (1ull << j);
    }
    g_mask[(size_t)i * NWORD + colb] = bits;
}

// ---------------------------------------------------------------------------
__global__ void __launch_bounds__(256) nms_scan(float* __restrict__ out) {
    __shared__ u64 rem[NWORD];
    __shared__ u64 roww[64];
    __shared__ int selidx[64];
    const int t = threadIdx.x;
    for (int c = t; c < NWORD; c += 256) {
        u64 wv = 0;
        for (int b = 0; b < 64; ++b) {
            int i = c * 64 + b;
            if (i >= NPRE || !g_valid[i]) wv |= (1ull << b);
        }
        rem[c] = wv;
    }
    u64 nxt = 0;
    if (t < 64) nxt = g_mask[(size_t)t * NWORD + 0];
    __syncthreads();
    int cnt = 0;
    for (int c = 0; c < NWORD && cnt < NPOST; ++c) {
        if (t < 64) roww[t] = nxt;
        __syncthreads();
        u64 alive = ~rem[c];
        int ns = 0;
        while (alive && cnt < NPOST) {
            int b = __ffsll((long long)alive) - 1;
            int i = c * 64 + b;
            if (t < 4) out[OFF_ROIS + cnt * 4 + t] = g_sboxes[i * 4 + t];
            if (t == 0) selidx[ns] = i;
            ns++;
            cnt++;
            alive &= ~roww[b];
            alive &= ~(1ull << b);
        }
        __syncthreads();
        if (t < 64 && c + 1 < NWORD) {
            int ib = (c + 1) * 64 + t;
            nxt = (ib < NPRE) ? g_mask[(size_t)ib * NWORD + (c + 1)] : 0ull;
        }
        if (ns) {
            for (int wd = c + 1 + t; wd < NWORD; wd += 256) {
                u64 a = rem[wd];
                int k = 0;
                for (; k + 8 <= ns; k += 8) {
                    u64 m0 = g_mask[(size_t)selidx[k + 0] * NWORD + wd];
                    u64 m1 = g_mask[(size_t)selidx[k + 1] * NWORD + wd];
                    u64 m2 = g_mask[(size_t)selidx[k + 2] * NWORD + wd];
                    u64 m3 = g_mask[(size_t)selidx[k + 3] * NWORD + wd];
                    u64 m4 = g_mask[(size_t)selidx[k + 4] * NWORD + wd];
                    u64 m5 = g_mask[(size_t)selidx[k + 5] * NWORD + wd];
                    u64 m6 = g_mask[(size_t)selidx[k + 6] * NWORD + wd];
                    u64 m7 = g_mask[(size_t)selidx[k + 7] * NWORD + wd];
                    a |= ((m0 | m1) | (m2 | m3)) | ((m4 | m5) | (m6 | m7));
                }
                for (; k < ns; ++k)
                    a |= g_mask[(size_t)selidx[k] * NWORD + wd];
                rem[wd] = a;
            }
        }
        __syncthreads();
    }
    for (int i2 = cnt * 4 + t; i2 < NPOST * 4; i2 += 256)
        out[OFF_ROIS + i2] = 0.f;
}

// ---------------------------------------------------------------------------
extern "C" void kernel_launch(void* const* d_in, const int* in_sizes, int n_in,
                              void* d_out, int out_size) {
    const float* x       = (const float*)d_in[0];
    const float* conv_w  = (const float*)d_in[1];
    const float* conv_b  = (const float*)d_in[2];
    const float* score_w = (const float*)d_in[3];
    const float* score_b = (const float*)d_in[4];
    const float* loc_w   = (const float*)d_in[5];
    const float* loc_b   = (const float*)d_in[6];
    const int*   imh     = (const int*)d_in[7];
    const int*   imw     = (const int*)d_in[8];
    float* out = (float*)d_out;

    static int smem_set = 0;
    if (!smem_set) {
        cudaFuncSetAttribute(conv3_lrelu, cudaFuncAttributeMaxDynamicSharedMemorySize,
                             CONV_SMEM_FLOATS * 4);
        smem_set = 1;
    }

    // my launch idx:   0         1        2        3 (= ncu idx 5 -> nms_mask profiled)
    zero_rois<<<(NPOST * 4 + 255) / 256, 256>>>(out);
    prep_wt<<<dim3(288, 16), 256>>>(conv_w);
    prep_w<<<(512 * 56 + 255) / 256, 256>>>(score_w, loc_w);
    nms_mask<<<dim3(NWORD, 47), 256>>>();   // measurement pre-run (overwritten below)

    conv3_lrelu<<<dim3(8, 32), 256, CONV_SMEM_FLOATS * 4>>>(x, conv_b);
    heads_kernel<<<128, 256>>>(out, loc_b, score_b);
    decode_kernel<<<SORTN / 256, 256>>>(out);
    megasort<<<16, 1024>>>(imh, imw);
    nms_mask<<<dim3(NWORD, 47), 256>>>();
    // nms_scan x3: idempotent; delta vs R15 isolates scan cost (2x extra)
    nms_scan<<<1, 256>>>(out);
    nms_scan<<<1, 256>>>(out);
    nms_scan<<<1, 256>>>(out);
}

// round 17
// speedup vs baseline: 1.7308x; 1.7308x over previous
#include <cuda_runtime.h>
#include <math.h>

typedef unsigned int u32;
typedef unsigned long long u64;

#define CIN   1024
#define COUT  512
#define NPIX  4096
#define NANCH 36864
#define SORTN 65536
#define NPRE  12000
#define NPOST 2000
#define NWORD 188   /* ceil(12000/64) = 47*4 */
#define NGRP  47

#define OFF_LOC  0
#define OFF_SC   147456
#define OFF_ROIS 221184
#define OFF_ANC  229184

#define XSTR 68
#define XIC  (4 * XSTR)
#define XS_FLOATS (8 * XIC)
#define WS_FLOATS (72 * 64)
#define CONV_SMEM_FLOATS (2 * XS_FLOATS + 2 * WS_FLOATS)   /* 54272 B */

__device__ __align__(16) float g_h[COUT * NPIX];
__device__ __align__(16) float g_wt[9216 * 512];
__device__ __align__(16) float g_wh[COUT * 56];
__device__ __align__(16) float g_boxes[NANCH * 4];
__device__ u64 g_keys[SORTN];
__device__ __align__(16) float g_sboxes[NPRE * 4];
__device__ int g_valid[NPRE];
__device__ u64 g_mask[(size_t)NPRE * NWORD];
__device__ unsigned g_barcnt = 0;
__device__ unsigned g_bargen = 0;

#define FMA2(d, a, b) asm("fma.rn.f32x2 %0, %1, %2, %0;" : "+l"(d) : "l"(a), "l"(b))
#define ADD2(d, a, b) asm("add.rn.f32x2 %0, %1, %2;" : "=l"(d) : "l"(a), "l"(b))
#define PK2(d, lo, hi) asm("mov.b64 %0, {%1, %2};" : "=l"(d) : "f"(lo), "f"(hi))
#define UPK2(lo, hi, s) asm("mov.b64 {%0, %1}, %2;" : "=f"(lo), "=f"(hi) : "l"(s))
#define NEGMASK2 0x8000000080000000ull

#define CP_ASYNC4(dst_u32, src_ptr, srcsz) \
    asm volatile("cp.async.ca.shared.global [%0], [%1], 4, %2;" \
                 :: "r"(dst_u32), "l"(src_ptr), "r"(srcsz))
#define CP_COMMIT()  asm volatile("cp.async.commit_group;")
#define CP_WAIT0()   asm volatile("cp.async.wait_group 0;" ::: "memory")

// ---------------------------------------------------------------------------
__global__ void zero_rois(float* __restrict__ out) {
    int i = blockIdx.x * 256 + threadIdx.x;
    if (i < NPOST * 4) out[OFF_ROIS + i] = 0.f;
}

// ---------------------------------------------------------------------------
__global__ void __launch_bounds__(256) prep_wt(const float* __restrict__ w) {
    __shared__ float tile[32][33];
    const int j0  = blockIdx.x * 32;
    const int oc0 = blockIdx.y * 32;
    const int tx = threadIdx.x & 31, ty = threadIdx.x >> 5;
#pragma unroll
    for (int r = 0; r < 4; ++r)
        tile[ty + r * 8][tx] = w[(size_t)(oc0 + ty + r * 8) * 9216 + j0 + tx];
    __syncthreads();
#pragma unroll
    for (int r = 0; r < 4; ++r)
        g_wt[(size_t)(j0 + ty + r * 8) * 512 + oc0 + tx] = tile[tx][ty + r * 8];
}

// ---------------------------------------------------------------------------
__global__ void prep_w(const float* __restrict__ score_w, const float* __restrict__ loc_w) {
    int idx = blockIdx.x * 256 + threadIdx.x;
    if (idx >= 512 * 56) return;
    int c = idx / 56, o = idx - c * 56;
    float v = 0.f;
    if (o < 36) v = loc_w[o * 512 + c];
    else if (o < 54) v = score_w[(o - 36) * 512 + c];
    g_wh[idx] = v;
}

// ---------------------------------------------------------------------------
__device__ __forceinline__ void conv_stage(const float* __restrict__ x,
                                           int y0, int chunk, int oc0,
                                           u32 xs_u, u32 ws_u,
                                           int x_ic0, int x_r0, int x_c0, int tid) {
    const int ic0 = chunk << 3;
    {
        int ic = x_ic0, r = x_r0, cc = x_c0;
        int sidx = tid;
#pragma unroll
        for (int l = 0; l < 9; ++l) {
            if (ic < 8) {
                int iy  = y0 - 1 + r;
                int ixc = cc - 1;
                bool ok = (cc < 66) && ((unsigned)iy < 64u) && ((unsigned)ixc < 64u);
                const float* src = ok ? (x + (ic0 + ic) * 4096 + iy * 64 + ixc) : x;
                unsigned ss = ok ? 4u : 0u;
                CP_ASYNC4(xs_u + sidx * 4, src, ss);
            }
            sidx += 256;
            cc += 52; r += 3;
            if (cc >= XSTR) { cc -= XSTR; r += 1; }
            if (r >= 4) { r -= 4; ic += 1; }
        }
    }
    {
        const size_t base = (size_t)(ic0 * 9) * 512 + oc0;
#pragma unroll
        for (int l = 0; l < 18; ++l) {
            int idx = tid + l * 256;
            int k = idx >> 6, oc = idx & 63;
            CP_ASYNC4(ws_u + idx * 4, &g_wt[base + (size_t)k * 512 + oc], 4u);
        }
    }
    CP_COMMIT();
}

// ---------------------------------------------------------------------------
__global__ void __launch_bounds__(256, 2) conv3_lrelu(const float* __restrict__ x,
                                                      const float* __restrict__ bias) {
    extern __shared__ float dsm[];
    float* xsb[2] = { dsm, dsm + XS_FLOATS };
    float* wsb[2] = { dsm + 2 * XS_FLOATS, dsm + 2 * XS_FLOATS + WS_FLOATS };
    const u32 dsm_u = (u32)__cvta_generic_to_shared(dsm);
    const u32 xs_u[2] = { dsm_u, dsm_u + XS_FLOATS * 4 };
    const u32 ws_u[2] = { dsm_u + 2 * XS_FLOATS * 4, dsm_u + (2 * XS_FLOATS + WS_FLOATS) * 4 };

    const int oc0 = blockIdx.x * 64;
    const int y0  = blockIdx.y * 2;
    const int tid = threadIdx.x;
    const int tx = tid & 15, ty = tid >> 4;
    const int ry  = tx >> 3;
    const int cx0 = (tx & 7) << 3;
    const int ocl = ty << 2;

    u64 part2[2][8], acc2[2][8], ncmp2[2][8];
#pragma unroll
    for (int o = 0; o < 2; ++o)
#pragma unroll
        for (int p = 0; p < 8; ++p) { part2[o][p] = 0ull; acc2[o][p] = 0ull; ncmp2[o][p] = 0ull; }

    const int x_ic0 = tid / XIC;
    const int x_rem0 = tid - x_ic0 * XIC;
    const int x_r0 = x_rem0 / XSTR;
    const int x_c0 = x_rem0 - x_r0 * XSTR;

    conv_stage(x, y0, 0, oc0, xs_u[0], ws_u[0], x_ic0, x_r0, x_c0, tid);
    CP_WAIT0();
    __syncthreads();

#pragma unroll 1
    for (int chunk = 0; chunk < CIN / 8; ++chunk) {
        const int cur = chunk & 1;
        if (chunk + 1 < CIN / 8)
            conv_stage(x, y0, chunk + 1, oc0, xs_u[1 - cur], ws_u[1 - cur],
                       x_ic0, x_r0, x_c0, tid);
        const float* xs = xsb[cur];
        const float* ws = wsb[cur];
#pragma unroll 1
        for (int ic = 0; ic < 8; ++ic) {
#pragma unroll
            for (int ky = 0; ky < 3; ++ky) {
                const float4* xr = (const float4*)&xs[ic * XIC + (ry + ky) * XSTR + cx0];
                float xv[12];
                *(float4*)(xv)     = xr[0];
                *(float4*)(xv + 4) = xr[1];
                *(float4*)(xv + 8) = xr[2];
                u64 xb[10];
#pragma unroll
                for (int i = 0; i < 10; ++i) PK2(xb[i], xv[i], xv[i]);
#pragma unroll
                for (int kx = 0; kx < 3; ++kx) {
                    const float4 wq = *(const float4*)&ws[(ic * 9 + ky * 3 + kx) * 64 + ocl];
                    u64 wp0, wp1;
                    PK2(wp0, wq.x, wq.y);
                    PK2(wp1, wq.z, wq.w);
#pragma unroll
                    for (int p = 0; p < 8; ++p) {
                        FMA2(part2[0][p], wp0, xb[p + kx]);
                        FMA2(part2[1][p], wp1, xb[p + kx]);
                    }
                }
            }
        }
        if (chunk & 1) {
#pragma unroll
            for (int o = 0; o < 2; ++o)
#pragma unroll
                for (int p = 0; p < 8; ++p) {
                    u64 y, t, s;
                    ADD2(y, part2[o][p], ncmp2[o][p]);
                    ADD2(t, acc2[o][p], y);
                    u64 tn = t ^ NEGMASK2;
                    ADD2(s, acc2[o][p], tn);
                    ADD2(ncmp2[o][p], s, y);
                    acc2[o][p] = t;
                    part2[o][p] = 0ull;
                }
        }
        if (chunk + 1 < CIN / 8) CP_WAIT0();
        __syncthreads();
    }
    const int row = y0 + ry;
#pragma unroll
    for (int o = 0; o < 2; ++o)
#pragma unroll
        for (int p = 0; p < 8; ++p) {
            float a0, a1;
            UPK2(a0, a1, acc2[o][p]);
            int oc = oc0 + ocl + 2 * o;
            float v0 = a0 + bias[oc];
            float v1 = a1 + bias[oc + 1];
            v0 = v0 > 0.f ? v0 : 0.01f * v0;
            v1 = v1 > 0.f ? v1 : 0.01f * v1;
            g_h[oc * 4096 + row * 64 + cx0 + p] = v0;
            g_h[(oc + 1) * 4096 + row * 64 + cx0 + p] = v1;
        }
}

// ---------------------------------------------------------------------------
__global__ void __launch_bounds__(256) heads_kernel(float* __restrict__ out,
                                                    const float* __restrict__ loc_b,
                                                    const float* __restrict__ score_b) {
    __shared__ float hs[64 * 32];
    __shared__ float wsm[64 * 56];
    const int px0 = blockIdx.x * 32;
    const int tid = threadIdx.x;
    const int px = tid & 31, lane = tid >> 5;
    float acc[7], comp[7];
#pragma unroll
    for (int j = 0; j < 7; ++j) { acc[j] = 0.f; comp[j] = 0.f; }

    for (int ch = 0; ch < 8; ++ch) {
        const int c0 = ch * 64;
#pragma unroll
        for (int l = 0; l < 8; ++l) {
            int idx = tid + l * 256;
            int c = idx >> 5, pp = idx & 31;
            hs[idx] = g_h[(c0 + c) * 4096 + px0 + pp];
        }
#pragma unroll
        for (int l = 0; l < 14; ++l) {
            int idx = tid + l * 256;
            wsm[idx] = g_wh[c0 * 56 + idx];
        }
        __syncthreads();
        float part[7];
#pragma unroll
        for (int j = 0; j < 7; ++j) part[j] = 0.f;
#pragma unroll 4
        for (int c = 0; c < 64; ++c) {
            float hv = hs[c * 32 + px];
#pragma unroll
            for (int j = 0; j < 7; ++j)
                part[j] = __fmaf_rn(hv, wsm[c * 56 + lane * 7 + j], part[j]);
        }
#pragma unroll
        for (int j = 0; j < 7; ++j) {
            float y = __fsub_rn(part[j], comp[j]);
            float t = __fadd_rn(acc[j], y);
            comp[j] = __fsub_rn(__fsub_rn(t, acc[j]), y);
            acc[j] = t;
        }
        __syncthreads();
    }
    const int p = px0 + px;
#pragma unroll
    for (int j = 0; j < 7; ++j) {
        int o = lane * 7 + j;
        if (o < 36) {
            int a = o >> 2, cc = o & 3;
            out[OFF_LOC + (p * 9 + a) * 4 + cc] = acc[j] + loc_b[o];
        } else if (o < 54) {
            int s = o - 36;
            int a = s >> 1, cc = s & 1;
            out[OFF_SC + (p * 9 + a) * 2 + cc] = acc[j] + score_b[s];
        }
    }
}

// ---------------------------------------------------------------------------
__global__ void decode_kernel(float* __restrict__ out) {
    int idx = blockIdx.x * 256 + threadIdx.x;
    if (idx >= SORTN) return;
    if (idx >= NANCH) { g_keys[idx] = ~0ull; return; }

    int a = idx % 9;
    int p = idx / 9;
    int yy = p >> 6, xx = p & 63;

    const double ratios[3] = {0.5, 1.0, 2.0};
    const double scales[3] = {8.0, 16.0, 32.0};
    double r = ratios[a / 3], s = scales[a % 3];
    double hh = 16.0 * s * sqrt(r);
    double ww = 16.0 * s * sqrt(1.0 / r);
    float by1 = (float)(8.0 - hh / 2.0);
    float bx1 = (float)(8.0 - ww / 2.0);
    float by2 = (float)(8.0 + hh / 2.0);
    float bx2 = (float)(8.0 + ww / 2.0);
    float sy = (float)yy * 16.0f, sx = (float)xx * 16.0f;
    float a0 = sy + by1, a1 = sx + bx1, a2 = sy + by2, a3 = sx + bx2;

    out[OFF_ANC + idx * 4 + 0] = a0;
    out[OFF_ANC + idx * 4 + 1] = a1;
    out[OFF_ANC + idx * 4 + 2] = a2;
    out[OFF_ANC + idx * 4 + 3] = a3;

    float l0 = out[OFF_LOC + idx * 4 + 0];
    float l1 = out[OFF_LOC + idx * 4 + 1];
    float l2 = out[OFF_LOC + idx * 4 + 2];
    float l3 = out[OFF_LOC + idx * 4 + 3];
    float s0 = out[OFF_SC + idx * 2 + 0];
    float s1 = out[OFF_SC + idx * 2 + 1];

    double d0 = (double)s0, d1 = (double)s1;
    double m  = fmax(d0, d1);
    double e0 = exp(d0 - m), e1 = exp(d1 - m);
    float fg = (float)(e1 / (e0 + e1));

    float ha = a2 - a0, wa = a3 - a1;
    float cya = a0 + 0.5f * ha, cxa = a1 + 0.5f * wa;
    float cy = l0 * ha + cya;
    float cx = l1 * wa + cxa;
    float bh = ha * expf(l2);
    float bw = wa * expf(l3);
    g_boxes[idx * 4 + 0] = cy - 0.5f * bh;
    g_boxes[idx * 4 + 1] = cx - 0.5f * bw;
    g_boxes[idx * 4 + 2] = cy + 0.5f * bh;
    g_boxes[idx * 4 + 3] = cx + 0.5f * bw;

    unsigned ub = __float_as_uint(fg);
    g_keys[idx] = ((u64)(ub ^ 0xFFFFFFFFu) << 32) | (unsigned)idx;
}

// ---------------------------------------------------------------------------
__device__ __forceinline__ void cmpswap(u64& a, u64& b, bool up) {
    if ((a > b) == up) { u64 t = a; a = b; b = t; }
}

__device__ __forceinline__ void gridbar() {
    __syncthreads();
    if (threadIdx.x == 0) {
        __threadfence();
        unsigned gen = atomicAdd(&g_bargen, 0u);
        if (atomicAdd(&g_barcnt, 1u) == gridDim.x - 1) {
            g_barcnt = 0;
            __threadfence();
            atomicAdd(&g_bargen, 1u);
        } else {
            while (atomicAdd(&g_bargen, 0u) == gen) {}
        }
        __threadfence();
    }
    __syncthreads();
}

__device__ __forceinline__ void local_step(u64* s, int base, int j, int k, int t) {
#pragma unroll
    for (int m = 0; m < 2; ++m) {
        int pr = t + m * 1024;
        int i = ((pr & ~(j - 1)) << 1) | (pr & (j - 1));
        int p = i | j;
        bool up = (((base + i) & k) == 0);
        u64 a = s[i], b = s[p];
        if ((a > b) == up) { s[i] = b; s[p] = a; }
    }
}

__global__ void __launch_bounds__(1024) megasort(const int* __restrict__ imh,
                                                 const int* __restrict__ imw) {
    __shared__ u64 s[4096];
    const int b = blockIdx.x;
    const int base = b * 4096;
    const int t = threadIdx.x;
    const int gq = b * 1024 + t;

#pragma unroll
    for (int m = 0; m < 4; ++m) s[t + m * 1024] = g_keys[base + t + m * 1024];
    __syncthreads();

    for (int k = 2; k <= 4096; k <<= 1)
        for (int j = k >> 1; j > 0; j >>= 1) { local_step(s, base, j, k, t); __syncthreads(); }

    for (int k = 8192; k <= 65536; k <<= 1) {
#pragma unroll
        for (int m = 0; m < 4; ++m) g_keys[base + t + m * 1024] = s[t + m * 1024];
        gridbar();
        int j = k >> 1;
        while (j >= 4096) {
            if (j >= 8192) {
                int a = j >> 1;
                int low = gq & (a - 1);
                int i = ((gq & ~(a - 1)) << 2) | low;
                u64 v0 = g_keys[i];
                u64 v1 = g_keys[i + a];
                u64 v2 = g_keys[i + 2 * a];
                u64 v3 = g_keys[i + 3 * a];
                bool up = ((i & k) == 0);
                cmpswap(v0, v2, up); cmpswap(v1, v3, up);
                cmpswap(v0, v1, up); cmpswap(v2, v3, up);
                g_keys[i] = v0;
                g_keys[i + a] = v1;
                g_keys[i + 2 * a] = v2;
                g_keys[i + 3 * a] = v3;
                j >>= 2;
            } else {
#pragma unroll
                for (int m = 0; m < 2; ++m) {
                    int p = gq + m * 16384;
                    int i = ((p & ~(j - 1)) << 1) | (p & (j - 1));
                    int q = i | j;
                    bool up = ((i & k) == 0);
                    u64 a = g_keys[i], bb = g_keys[q];
                    if ((a > bb) == up) { g_keys[i] = bb; g_keys[q] = a; }
                }
                j >>= 1;
            }
            gridbar();
        }
#pragma unroll
        for (int m = 0; m < 4; ++m) s[t + m * 1024] = g_keys[base + t + m * 1024];
        __syncthreads();
        for (int j2 = 2048; j2 > 0; j2 >>= 1) { local_step(s, base, j2, k, t); __syncthreads(); }
    }

    if (base < NPRE) {
        float H = (float)(*imh), W = (float)(*imw);
#pragma unroll
        for (int m = 0; m < 4; ++m) {
            int gi = base + t + m * 1024;
            if (gi < NPRE) {
                unsigned idx = (unsigned)s[t + m * 1024];
                float b0 = g_boxes[idx * 4 + 0];
                float b1 = g_boxes[idx * 4 + 1];
                float b2 = g_boxes[idx * 4 + 2];
                float b3 = g_boxes[idx * 4 + 3];
                b0 = fminf(fmaxf(b0, 0.f), H);
                b1 = fminf(fmaxf(b1, 0.f), W);
                b2 = fminf(fmaxf(b2, 0.f), H);
                b3 = fminf(fmaxf(b3, 0.f), W);
                g_sboxes[gi * 4 + 0] = b0;
                g_sboxes[gi * 4 + 1] = b1;
                g_sboxes[gi * 4 + 2] = b2;
                g_sboxes[gi * 4 + 3] = b3;
                g_valid[gi] = ((b2 - b0) >= 16.f) && ((b3 - b1) >= 16.f);
            }
        }
    }
}

// ---------------------------------------------------------------------------
// NMS bitmask: guard-banded threshold (division only in a ~2e-5 band)
// ---------------------------------------------------------------------------
__global__ void __launch_bounds__(256) nms_mask() {
    const int colb = blockIdx.x;
    const int rowb4 = blockIdx.y;
    if (colb < rowb4 * 4) return;
    __shared__ float cby1[64], cbx1[64], cby2[64], cbx2[64], cbar[64];
    const int cbase = colb * 64;
    const int cs = min(64, NPRE - cbase);
    const int t = threadIdx.x;
    if (t < cs) {
        float4 v = ((const float4*)g_sboxes)[cbase + t];
        cby1[t] = v.x; cbx1[t] = v.y; cby2[t] = v.z; cbx2[t] = v.w;
        cbar[t] = (v.z - v.x) * (v.w - v.y);
    }
    __syncthreads();
    const int rowb = rowb4 * 4 + (t >> 6);
    const int tr = t & 63;
    if (colb < rowb) return;
    const int i = rowb * 64 + tr;
    if (i >= NPRE) return;
    float y1 = g_sboxes[i * 4 + 0], x1 = g_sboxes[i * 4 + 1];
    float y2 = g_sboxes[i * 4 + 2], x2 = g_sboxes[i * 4 + 3];
    float ai = (y2 - y1) * (x2 - x1);
    u64 bits = 0;
    int j0 = (rowb == colb) ? (tr + 1) : 0;
    for (int j = j0; j < cs; ++j) {
        float yy1 = fmaxf(y1, cby1[j]), xx1 = fmaxf(x1, cbx1[j]);
        float yy2 = fminf(y2, cby2[j]), xx2 = fminf(x2, cbx2[j]);
        float inter = fmaxf(yy2 - yy1, 0.f) * fmaxf(xx2 - xx1, 0.f);
        float denom = ai + cbar[j] - inter + 1e-10f;
        float thr = 0.7f * denom;
        bool sup;
        if (inter > thr * 1.00002f) sup = true;
        else if (inter < thr * 0.99998f) sup = false;
        else sup = (inter / denom > 0.7f);      // exact path, rare
        if (sup) bits |= (1ull << j);
    }
    g_mask[(size_t)i * NWORD + colb] = bits;
}

// ---------------------------------------------------------------------------
// greedy-NMS scan: 256-box groups (4 u64 words/iteration), batched updates.
// Lower-triangle mask words are never written (stay 0), so cross-word ANDs
// in the pop loop are exact. Words processed in ascending order -> greedy
// order preserved bit-for-bit.
// ---------------------------------------------------------------------------
__global__ void __launch_bounds__(256) nms_scan(float* __restrict__ out) {
    __shared__ u64 rem[NWORD];
    __shared__ __align__(16) u64 roww4[256][4];
    __shared__ int sel[NPOST];
    const int t = threadIdx.x;
    for (int c = t; c < NWORD; c += 256) {
        u64 wv = 0;
        for (int b = 0; b < 64; ++b) {
            int i = c * 64 + b;
            if (i >= NPRE || !g_valid[i]) wv |= (1ull << b);
        }
        rem[c] = wv;
    }
    __syncthreads();
    int cnt = 0;
    for (int g = 0; g < NGRP && cnt < NPOST; ++g) {
        const int cw = g * 4;
        // load in-group suppression rows (box g*256+t, words cw..cw+3)
        {
            int ib = g * 256 + t;
            if (ib < NPRE) {
                const u64* row = &g_mask[(size_t)ib * NWORD + cw];
                roww4[t][0] = row[0];
                roww4[t][1] = row[1];
                roww4[t][2] = row[2];
                roww4[t][3] = row[3];
            } else {
                roww4[t][0] = 0; roww4[t][1] = 0; roww4[t][2] = 0; roww4[t][3] = 0;
            }
        }
        __syncthreads();
        u64 a0 = ~rem[cw], a1 = ~rem[cw + 1], a2 = ~rem[cw + 2], a3 = ~rem[cw + 3];
        const int nsbase = cnt;
        while (cnt < NPOST) {
            int tb;
            if (a0)      { tb =       __ffsll((long long)a0) - 1; a0 &= a0 - 1; }
            else if (a1) { tb =  64 + __ffsll((long long)a1) - 1; a1 &= a1 - 1; }
            else if (a2) { tb = 128 + __ffsll((long long)a2) - 1; a2 &= a2 - 1; }
            else if (a3) { tb = 192 + __ffsll((long long)a3) - 1; a3 &= a3 - 1; }
            else break;
            if (t == 0) sel[cnt] = g * 256 + tb;
            cnt++;
            a0 &= ~roww4[tb][0];
            a1 &= ~roww4[tb][1];
            a2 &= ~roww4[tb][2];
            a3 &= ~roww4[tb][3];
        }
        const int ns = cnt - nsbase;
        __syncthreads();                         // sel visible to all
        if (ns && cnt < NPOST) {
            for (int wd = cw + 4 + t; wd < NWORD; wd += 256) {
                u64 a = rem[wd];
                int k = 0;
                for (; k + 16 <= ns; k += 16) {
                    u64 m[16];
#pragma unroll
                    for (int q = 0; q < 16; ++q)
                        m[q] = g_mask[(size_t)sel[nsbase + k + q] * NWORD + wd];
#pragma unroll
                    for (int q = 0; q < 16; ++q) a |= m[q];
                }
                for (; k < ns; ++k)
                    a |= g_mask[(size_t)sel[nsbase + k] * NWORD + wd];
                rem[wd] = a;
            }
        }
        __syncthreads();
    }
    // flush rois (parallel) + zero fill
    for (int r = t; r < cnt; r += 256)
        ((float4*)(out + OFF_ROIS))[r] = ((const float4*)g_sboxes)[sel[r]];
    for (int i2 = cnt * 4 + t; i2 < NPOST * 4; i2 += 256)
        out[OFF_ROIS + i2] = 0.f;
}

// ---------------------------------------------------------------------------
extern "C" void kernel_launch(void* const* d_in, const int* in_sizes, int n_in,
                              void* d_out, int out_size) {
    const float* x       = (const float*)d_in[0];
    const float* conv_w  = (const float*)d_in[1];
    const float* conv_b  = (const float*)d_in[2];
    const float* score_w = (const float*)d_in[3];
    const float* score_b = (const float*)d_in[4];
    const float* loc_w   = (const float*)d_in[5];
    const float* loc_b   = (const float*)d_in[6];
    const int*   imh     = (const int*)d_in[7];
    const int*   imw     = (const int*)d_in[8];
    float* out = (float*)d_out;

    static int smem_set = 0;
    if (!smem_set) {
        cudaFuncSetAttribute(conv3_lrelu, cudaFuncAttributeMaxDynamicSharedMemorySize,
                             CONV_SMEM_FLOATS * 4);
        smem_set = 1;
    }

    // my launch idx:    0          1        2        3 (= ncu idx 5 -> conv profiled)
    zero_rois<<<(NPOST * 4 + 255) / 256, 256>>>(out);
    prep_wt<<<dim3(288, 16), 256>>>(conv_w);
    prep_w<<<(512 * 56 + 255) / 256, 256>>>(score_w, loc_w);
    conv3_lrelu<<<dim3(8, 32), 256, CONV_SMEM_FLOATS * 4>>>(x, conv_b);

    heads_kernel<<<128, 256>>>(out, loc_b, score_b);
    decode_kernel<<<SORTN / 256, 256>>>(out);
    megasort<<<16, 1024>>>(imh, imw);
    nms_mask<<<dim3(NWORD, 47), 256>>>();
    nms_scan<<<1, 256>>>(out);
}